// round 10
// baseline (speedup 1.0000x reference)
#include <cuda_runtime.h>
#include <math.h>
#include <stdint.h>

#define N_NODES 4096
#define F_IN    1024
#define HID     256
#define OUT_D   16
#define ALPHA   0.2f
#define NEG_INF (-3.4e38f)
#define MAXE    64
#define GEMM_BLOCKS ((HID / 64) * (N_NODES / 64))   // 4*64 = 256
#define A_STR   36
#define B_STR   72
#define ABUF_FLOATS (2 * 64 * A_STR)                // 4608
#define BBUF_FLOATS (2 * 32 * B_STR)                // 4608
#define DYN_SMEM ((ABUF_FLOATS + BBUF_FLOATS) * 4)  // 36864 bytes

// ---------------- scratch (device globals; no allocation) ----------------
__device__ float g_h1[N_NODES * HID];
__device__ float g_h2[N_NODES * OUT_D];
__device__ float g_z [N_NODES * OUT_D];
__device__ float g_s1p[4 * N_NODES], g_t1p[4 * N_NODES];  // per-col-quadrant dots
__device__ float g_s2[N_NODES], g_t2[N_NODES];
__device__ int   g_cnt[N_NODES];
__device__ int   g_ej [N_NODES * MAXE];
__device__ float g_ew [N_NODES * MAXE];

// ================= tf32 / cp.async helpers ================================
__device__ __forceinline__ uint32_t cvt_tf32(float x) {
    uint32_t r;
    asm("cvt.rna.tf32.f32 %0, %1;" : "=r"(r) : "f"(x));
    return r;
}
__device__ __forceinline__ void mma_tf32(float c[4], uint32_t a0, uint32_t a1,
                                         uint32_t a2, uint32_t a3,
                                         uint32_t b0, uint32_t b1) {
    asm volatile(
        "mma.sync.aligned.m16n8k8.row.col.f32.tf32.tf32.f32 "
        "{%0,%1,%2,%3}, {%4,%5,%6,%7}, {%8,%9}, {%0,%1,%2,%3};"
        : "+f"(c[0]), "+f"(c[1]), "+f"(c[2]), "+f"(c[3])
        : "r"(a0), "r"(a1), "r"(a2), "r"(a3), "r"(b0), "r"(b1));
}
__device__ __forceinline__ void cp16(uint32_t smem_dst, const float* gmem_src) {
    asm volatile("cp.async.cg.shared.global [%0], [%1], 16;" :: "r"(smem_dst), "l"(gmem_src));
}
__device__ __forceinline__ void cp_commit() {
    asm volatile("cp.async.commit_group;");
}
template <int N>
__device__ __forceinline__ void cp_wait() {
    asm volatile("cp.async.wait_group %0;" :: "n"(N));
}

// ================= f32x2 packed helpers (sm_100+) =========================
__device__ __forceinline__ unsigned long long splat2(float x) {
    unsigned long long r;
    asm("mov.b64 %0, {%1, %1};" : "=l"(r) : "f"(x));
    return r;
}
__device__ __forceinline__ unsigned long long fma2(unsigned long long a,
                                                   unsigned long long b,
                                                   unsigned long long c) {
    unsigned long long d;
    asm("fma.rn.f32x2 %0, %1, %2, %3;" : "=l"(d) : "l"(a), "l"(b), "l"(c));
    return d;
}
__device__ __forceinline__ unsigned long long mul2(unsigned long long a,
                                                   unsigned long long b) {
    unsigned long long d;
    asm("mul.rn.f32x2 %0, %1, %2;" : "=l"(d) : "l"(a), "l"(b));
    return d;
}
__device__ __forceinline__ void unpack2(unsigned long long v, float& lo, float& hi) {
    asm("mov.b64 {%0, %1}, %2;" : "=f"(lo), "=f"(hi) : "l"(v));
}

// ====== FUSED: blocks [0,256): tf32 full-K GEMM -> h1 + quadrant rowdots;
//        blocks [256,4352): edge-list scan of m ============================
__global__ void __launch_bounds__(256) gemm_edges(
        const float* __restrict__ A, const float* __restrict__ B,
        const float* __restrict__ as1, const float* __restrict__ an1,
        float* __restrict__ H, float* __restrict__ s1p, float* __restrict__ t1p,
        const float* __restrict__ M, int* __restrict__ cnt,
        int* __restrict__ ej, float* __restrict__ ew) {
    extern __shared__ float dsm[];
    __shared__ int wsum[8], wbase[8];

    int bid = blockIdx.x, tid = threadIdx.x;
    if (bid < GEMM_BLOCKS) {
        float* Asf = dsm;                  // [2][64][A_STR]
        float* Bsf = dsm + ABUF_FLOATS;    // [2][32][B_STR]
        uint32_t sa_base = (uint32_t)__cvta_generic_to_shared(Asf);
        uint32_t sb_base = (uint32_t)__cvta_generic_to_shared(Bsf);
        __shared__ float as_sh[64], an_sh[64];
        __shared__ float sred[64][2], tred[64][2];

        int bx = bid & 3;                  // col quadrant (HID/64 = 4)
        int by = bid >> 2;                 // row tile (64)
        int warp = tid >> 5, lane = tid & 31;
        int grp = lane >> 2, tid4 = lane & 3;
        int wm = warp >> 1, wn = warp & 1; // warp tile 16m x 32n
        int rowBase = by * 64, colBase = bx * 64;
        const int NIT = F_IN / 32;         // 32

        if (tid < 64) {
            as_sh[tid] = as1[colBase + tid];
            an_sh[tid] = an1[colBase + tid];
        }

        // per-thread load coordinates (fixed across iters)
        int a_r0 = tid >> 3,         a_c0 = (tid & 7) * 4;
        int a_r1 = (tid >> 3) + 32;
        int b_r0 = tid >> 4,         b_c0 = (tid & 15) * 4;
        int b_r1 = b_r0 + 16;

        float acc[4][4];
#pragma unroll
        for (int nt = 0; nt < 4; nt++)
#pragma unroll
            for (int q = 0; q < 4; q++) acc[nt][q] = 0.f;

        // ---- prologue: stage iter 0 into buffer 0
        {
            cp16(sa_base + (uint32_t)((a_r0 * A_STR + a_c0) * 4),
                 &A[(size_t)(rowBase + a_r0) * F_IN + a_c0]);
            cp16(sa_base + (uint32_t)((a_r1 * A_STR + a_c0) * 4),
                 &A[(size_t)(rowBase + a_r1) * F_IN + a_c0]);
            cp16(sb_base + (uint32_t)((b_r0 * B_STR + b_c0) * 4),
                 &B[(size_t)b_r0 * HID + colBase + b_c0]);
            cp16(sb_base + (uint32_t)((b_r1 * B_STR + b_c0) * 4),
                 &B[(size_t)b_r1 * HID + colBase + b_c0]);
            cp_commit();
        }

        for (int it = 0; it < NIT; it++) {
            int cur = it & 1, nxt = cur ^ 1;
            if (it + 1 < NIT) {
                int k0 = (it + 1) * 32;
                uint32_t ao = (uint32_t)(nxt * 64 * A_STR * 4);
                uint32_t bo = (uint32_t)(nxt * 32 * B_STR * 4);
                cp16(sa_base + ao + (uint32_t)((a_r0 * A_STR + a_c0) * 4),
                     &A[(size_t)(rowBase + a_r0) * F_IN + k0 + a_c0]);
                cp16(sa_base + ao + (uint32_t)((a_r1 * A_STR + a_c0) * 4),
                     &A[(size_t)(rowBase + a_r1) * F_IN + k0 + a_c0]);
                cp16(sb_base + bo + (uint32_t)((b_r0 * B_STR + b_c0) * 4),
                     &B[(size_t)(k0 + b_r0) * HID + colBase + b_c0]);
                cp16(sb_base + bo + (uint32_t)((b_r1 * B_STR + b_c0) * 4),
                     &B[(size_t)(k0 + b_r1) * HID + colBase + b_c0]);
                cp_commit();
                cp_wait<1>();
            } else {
                cp_wait<0>();
            }
            __syncthreads();

            const float* Ab = Asf + cur * 64 * A_STR;
            const float* Bb = Bsf + cur * 32 * B_STR;
#pragma unroll
            for (int kk = 0; kk < 32; kk += 8) {
                int r0 = wm * 16 + grp;
                uint32_t a0 = cvt_tf32(Ab[r0 * A_STR + kk + tid4]);
                uint32_t a1 = cvt_tf32(Ab[(r0 + 8) * A_STR + kk + tid4]);
                uint32_t a2 = cvt_tf32(Ab[r0 * A_STR + kk + tid4 + 4]);
                uint32_t a3 = cvt_tf32(Ab[(r0 + 8) * A_STR + kk + tid4 + 4]);
                uint32_t b[4][2];
#pragma unroll
                for (int nt = 0; nt < 4; nt++) {
                    int cb = wn * 32 + nt * 8 + grp;
                    b[nt][0] = cvt_tf32(Bb[(kk + tid4) * B_STR + cb]);
                    b[nt][1] = cvt_tf32(Bb[(kk + tid4 + 4) * B_STR + cb]);
                }
#pragma unroll
                for (int nt = 0; nt < 4; nt++)
                    mma_tf32(acc[nt], a0, a1, a2, a3, b[nt][0], b[nt][1]);
            }
            __syncthreads();
        }

        // ---- epilogue: store h1 tile + quadrant rowdots --------------------
        int rA = rowBase + wm * 16 + grp;
#pragma unroll
        for (int nt = 0; nt < 4; nt++) {
            int c0 = colBase + wn * 32 + nt * 8 + tid4 * 2;
            *(float2*)&H[(size_t)rA * HID + c0]       = make_float2(acc[nt][0], acc[nt][1]);
            *(float2*)&H[(size_t)(rA + 8) * HID + c0] = make_float2(acc[nt][2], acc[nt][3]);
        }
#pragma unroll
        for (int half = 0; half < 2; half++) {
            float ps = 0.f, pt = 0.f;
#pragma unroll
            for (int nt = 0; nt < 4; nt++) {
                int cl = wn * 32 + nt * 8 + tid4 * 2;
                float v0 = acc[nt][half * 2 + 0];
                float v1 = acc[nt][half * 2 + 1];
                ps += v0 * as_sh[cl] + v1 * as_sh[cl + 1];
                pt += v0 * an_sh[cl] + v1 * an_sh[cl + 1];
            }
            ps += __shfl_xor_sync(0xffffffffu, ps, 1);
            pt += __shfl_xor_sync(0xffffffffu, pt, 1);
            ps += __shfl_xor_sync(0xffffffffu, ps, 2);
            pt += __shfl_xor_sync(0xffffffffu, pt, 2);
            if (tid4 == 0) {
                int rl = wm * 16 + grp + half * 8;
                sred[rl][wn] = ps;
                tred[rl][wn] = pt;
            }
        }
        __syncthreads();
        if (tid < 64) {
            s1p[(size_t)bx * N_NODES + rowBase + tid] = sred[tid][0] + sred[tid][1];
            t1p[(size_t)bx * N_NODES + rowBase + tid] = tred[tid][0] + tred[tid][1];
        }
    } else {
        // ---- edge extraction for row i (deterministic, sorted); streaming loads
        int i = bid - GEMM_BLOCKS;
        const float4* row = (const float4*)(M + (size_t)i * N_NODES);
        float4 v[4];
        int local = 0;
#pragma unroll
        for (int q = 0; q < 4; q++) {
            v[q] = __ldcs(&row[tid * 4 + q]);
            local += (v[q].x > 0.f) + (v[q].y > 0.f) + (v[q].z > 0.f) + (v[q].w > 0.f);
        }
        int lane = tid & 31, warp = tid >> 5;
        int sc = local;
#pragma unroll
        for (int o = 1; o < 32; o <<= 1) {
            int nb = __shfl_up_sync(0xffffffffu, sc, o);
            if (lane >= o) sc += nb;
        }
        if (lane == 31) wsum[warp] = sc;
        __syncthreads();
        if (tid < 8) {
            int b = 0;
            for (int w = 0; w < tid; w++) b += wsum[w];
            wbase[tid] = b;
        }
        __syncthreads();
        int off = wbase[warp] + sc - local;
        int rb = i * MAXE;
        int j0 = tid * 16;
#pragma unroll
        for (int q = 0; q < 4; q++) {
            float vals[4] = {v[q].x, v[q].y, v[q].z, v[q].w};
#pragma unroll
            for (int r = 0; r < 4; r++) {
                if (vals[r] > 0.f) {
                    if (off < MAXE) { ej[rb + off] = j0 + q * 4 + r; ew[rb + off] = vals[r]; }
                    off++;
                }
            }
        }
        if (tid == 0) {
            int total = wbase[7] + wsum[7];
            cnt[i] = total < MAXE ? total : MAXE;
        }
    }
}

// ====== layer-1 attention, warp-per-row ====================================
__device__ __forceinline__ float eluf(float x) { return x > 0.f ? x : expm1f(x); }

__global__ void __launch_bounds__(256) att1_fused(
        const int* __restrict__ cnt, const int* __restrict__ ej,
        const float* __restrict__ ew, const float* __restrict__ H,
        const float* __restrict__ s1p, const float* __restrict__ t1p,
        const float* __restrict__ W2,
        const float* __restrict__ as2, const float* __restrict__ an2,
        float* __restrict__ h2, float* __restrict__ s2, float* __restrict__ t2) {
    __shared__ float ws[8][MAXE];
    __shared__ int   jss[8][MAXE];
    int wl = threadIdx.x >> 5;
    int lane = threadIdx.x & 31;
    int i = blockIdx.x * 8 + wl;
    int n = cnt[i];
    float si = s1p[i] + s1p[N_NODES + i] + s1p[2 * N_NODES + i] + s1p[3 * N_NODES + i];

    float e0 = NEG_INF, e1 = NEG_INF;
    int j0 = 0, j1 = 0;
    if (lane < n) {
        j0 = ej[i * MAXE + lane];
        float w = ew[i * MAXE + lane];
        float tj = t1p[j0] + t1p[N_NODES + j0] + t1p[2 * N_NODES + j0] + t1p[3 * N_NODES + j0];
        float e = (si + tj) * w;
        e0 = e >= 0.f ? e : ALPHA * e;
    }
    if (lane + 32 < n) {
        j1 = ej[i * MAXE + lane + 32];
        float w = ew[i * MAXE + lane + 32];
        float tj = t1p[j1] + t1p[N_NODES + j1] + t1p[2 * N_NODES + j1] + t1p[3 * N_NODES + j1];
        float e = (si + tj) * w;
        e1 = e >= 0.f ? e : ALPHA * e;
    }
    float mx = fmaxf(e0, e1);
#pragma unroll
    for (int o = 16; o; o >>= 1) mx = fmaxf(mx, __shfl_xor_sync(0xffffffffu, mx, o));
    float w0 = (lane < n) ? __expf(e0 - mx) : 0.f;
    float w1 = (lane + 32 < n) ? __expf(e1 - mx) : 0.f;
    float sm = w0 + w1;
#pragma unroll
    for (int o = 16; o; o >>= 1) sm += __shfl_xor_sync(0xffffffffu, sm, o);
    float inv = 1.f / sm;
    ws[wl][lane] = w0 * inv;
    ws[wl][lane + 32] = w1 * inv;
    jss[wl][lane] = j0;
    jss[wl][lane + 32] = j1;
    __syncwarp();

    const float4* H4 = (const float4*)H;
    float4 acc0 = make_float4(0.f, 0.f, 0.f, 0.f);
    float4 acc1 = make_float4(0.f, 0.f, 0.f, 0.f);
    int n4 = (n + 3) & ~3;
    for (int p = 0; p < n4; p += 4) {
        float wA = ws[wl][p],     wB = ws[wl][p + 1];
        float wC = ws[wl][p + 2], wD = ws[wl][p + 3];
        size_t bA = (size_t)jss[wl][p] * 64,     bB = (size_t)jss[wl][p + 1] * 64;
        size_t bC = (size_t)jss[wl][p + 2] * 64, bD = (size_t)jss[wl][p + 3] * 64;
        float4 a0 = H4[bA + lane], a1 = H4[bA + 32 + lane];
        float4 b0 = H4[bB + lane], b1 = H4[bB + 32 + lane];
        float4 c0 = H4[bC + lane], c1 = H4[bC + 32 + lane];
        float4 d0 = H4[bD + lane], d1 = H4[bD + 32 + lane];
        acc0.x += wA * a0.x + wB * b0.x + wC * c0.x + wD * d0.x;
        acc0.y += wA * a0.y + wB * b0.y + wC * c0.y + wD * d0.y;
        acc0.z += wA * a0.z + wB * b0.z + wC * c0.z + wD * d0.z;
        acc0.w += wA * a0.w + wB * b0.w + wC * c0.w + wD * d0.w;
        acc1.x += wA * a1.x + wB * b1.x + wC * c1.x + wD * d1.x;
        acc1.y += wA * a1.y + wB * b1.y + wC * c1.y + wD * d1.y;
        acc1.z += wA * a1.z + wB * b1.z + wC * c1.z + wD * d1.z;
        acc1.w += wA * a1.w + wB * b1.w + wC * c1.w + wD * d1.w;
    }
    float o1v[8];
    o1v[0] = eluf(acc0.x); o1v[1] = eluf(acc0.y);
    o1v[2] = eluf(acc0.z); o1v[3] = eluf(acc0.w);
    o1v[4] = eluf(acc1.x); o1v[5] = eluf(acc1.y);
    o1v[6] = eluf(acc1.z); o1v[7] = eluf(acc1.w);

    float pa[16];
#pragma unroll
    for (int k = 0; k < 16; k++) pa[k] = 0.f;
#pragma unroll
    for (int half = 0; half < 2; half++) {
#pragma unroll
        for (int q = 0; q < 4; q++) {
            int c = half * 128 + 4 * lane + q;
            float ov = o1v[half * 4 + q];
            const float4* wr = (const float4*)&W2[c * OUT_D];
            float4 r0 = __ldg(wr), r1 = __ldg(wr + 1), r2 = __ldg(wr + 2), r3 = __ldg(wr + 3);
            pa[0] += ov * r0.x;  pa[1] += ov * r0.y;  pa[2] += ov * r0.z;  pa[3] += ov * r0.w;
            pa[4] += ov * r1.x;  pa[5] += ov * r1.y;  pa[6] += ov * r1.z;  pa[7] += ov * r1.w;
            pa[8] += ov * r2.x;  pa[9] += ov * r2.y;  pa[10] += ov * r2.z; pa[11] += ov * r2.w;
            pa[12] += ov * r3.x; pa[13] += ov * r3.y; pa[14] += ov * r3.z; pa[15] += ov * r3.w;
        }
    }
#pragma unroll
    for (int o = 16; o; o >>= 1)
#pragma unroll
        for (int k = 0; k < 16; k++)
            pa[k] += __shfl_xor_sync(0xffffffffu, pa[k], o);

    if (lane == 0) {
        *(float4*)&h2[(size_t)i * OUT_D]      = make_float4(pa[0], pa[1], pa[2], pa[3]);
        *(float4*)&h2[(size_t)i * OUT_D + 4]  = make_float4(pa[4], pa[5], pa[6], pa[7]);
        *(float4*)&h2[(size_t)i * OUT_D + 8]  = make_float4(pa[8], pa[9], pa[10], pa[11]);
        *(float4*)&h2[(size_t)i * OUT_D + 12] = make_float4(pa[12], pa[13], pa[14], pa[15]);
        float ps = 0.f, pt = 0.f;
#pragma unroll
        for (int k = 0; k < 16; k++) {
            ps += pa[k] * __ldg(&as2[k]);
            pt += pa[k] * __ldg(&an2[k]);
        }
        s2[i] = ps; t2[i] = pt;
    }
}

// ====== layer-2 attention + aggregate + ELU + L2-normalize (warp/row) ======
__global__ void att2_fused(const int* __restrict__ cnt, const int* __restrict__ ej,
                           const float* __restrict__ ew, const float* __restrict__ h2,
                           const float* __restrict__ s2, const float* __restrict__ t2,
                           float* __restrict__ z, float* __restrict__ zout) {
    __shared__ float ws[8][MAXE];
    __shared__ int   jss[8][MAXE];
    int wl = threadIdx.x >> 5;
    int lane = threadIdx.x & 31;
    int i = blockIdx.x * 8 + wl;
    int n = cnt[i];
    float si = s2[i];

    float e0 = NEG_INF, e1 = NEG_INF;
    int j0 = 0, j1 = 0;
    if (lane < n) {
        j0 = ej[i * MAXE + lane];
        float w = ew[i * MAXE + lane];
        float e = (si + t2[j0]) * w;
        e0 = e >= 0.f ? e : ALPHA * e;
    }
    if (lane + 32 < n) {
        j1 = ej[i * MAXE + lane + 32];
        float w = ew[i * MAXE + lane + 32];
        float e = (si + t2[j1]) * w;
        e1 = e >= 0.f ? e : ALPHA * e;
    }
    float mx = fmaxf(e0, e1);
#pragma unroll
    for (int o = 16; o; o >>= 1) mx = fmaxf(mx, __shfl_xor_sync(0xffffffffu, mx, o));
    float w0 = (lane < n) ? __expf(e0 - mx) : 0.f;
    float w1 = (lane + 32 < n) ? __expf(e1 - mx) : 0.f;
    float sm = w0 + w1;
#pragma unroll
    for (int o = 16; o; o >>= 1) sm += __shfl_xor_sync(0xffffffffu, sm, o);
    float inv = 1.f / sm;
    ws[wl][lane] = w0 * inv; ws[wl][lane + 32] = w1 * inv;
    jss[wl][lane] = j0; jss[wl][lane + 32] = j1;
    __syncwarp();

    int c = lane & 15, g = lane >> 4;
    float acc = 0.f;
    int n2 = (n + 1) & ~1;
    for (int p = g; p < n2; p += 2)
        acc += ws[wl][p] * h2[(size_t)jss[wl][p] * OUT_D + c];
    acc += __shfl_xor_sync(0xffffffffu, acc, 16);
    float o = eluf(acc);
    float sq = o * o;
#pragma unroll
    for (int off = 8; off; off >>= 1) sq += __shfl_xor_sync(0xffffffffu, sq, off);
    float invn = 1.f / fmaxf(sqrtf(sq), 1e-12f);
    float zz = o * invn;
    if (lane < 16) {
        z[(size_t)i * OUT_D + lane] = zz;
        zout[(size_t)i * OUT_D + lane] = zz;
    }
}

// ================= decoder: adj_pred = sigmoid(z @ z^T) ===================
__global__ void __launch_bounds__(256, 4) decoder(const float* __restrict__ z,
                                                  float* __restrict__ out) {
    __shared__ float zr[16][64];
    __shared__ float zc[16][128];
    int tid = threadIdx.x;
    int r0 = blockIdx.y * 64, c0 = blockIdx.x * 128;
    for (int p = tid; p < 64 * 16; p += 256) {
        int r = p >> 4, k = p & 15;
        zr[k][r] = z[(size_t)(r0 + r) * OUT_D + k];
    }
    for (int p = tid; p < 128 * 16; p += 256) {
        int r = p >> 4, k = p & 15;
        zc[k][r] = z[(size_t)(c0 + r) * OUT_D + k];
    }
    __syncthreads();
    int tx = tid & 31;
    int ty = tid >> 5;

    unsigned long long acc2[8][2];
#pragma unroll
    for (int i = 0; i < 8; i++) { acc2[i][0] = 0ull; acc2[i][1] = 0ull; }

#pragma unroll
    for (int k = 0; k < 16; k++) {
        ulonglong2 bc2 = *(const ulonglong2*)&zc[k][tx * 4];
#pragma unroll
        for (int i = 0; i < 8; i++) {
            unsigned long long ar2 = splat2(zr[k][ty * 8 + i]);
            acc2[i][0] = fma2(ar2, bc2.x, acc2[i][0]);
            acc2[i][1] = fma2(ar2, bc2.y, acc2[i][1]);
        }
    }

    const unsigned long long C8 = splat2(2.1357251e-5f);
    const unsigned long long C6 = splat2(-2.1081349e-4f);
    const unsigned long long C4 = splat2(2.0833333e-3f);
    const unsigned long long C2 = splat2(-2.0833333e-2f);
    const unsigned long long C0 = splat2(0.25f);
    const unsigned long long HALF = splat2(0.5f);

#pragma unroll
    for (int i = 0; i < 8; i++) {
        float4 v;
#pragma unroll
        for (int j = 0; j < 2; j++) {
            unsigned long long x = acc2[i][j];
            unsigned long long u = mul2(x, x);
            unsigned long long p = fma2(u, C8, C6);
            p = fma2(u, p, C4);
            p = fma2(u, p, C2);
            p = fma2(u, p, C0);
            p = fma2(x, p, HALF);
            if (j == 0) unpack2(p, v.x, v.y);
            else        unpack2(p, v.z, v.w);
        }
        *(float4*)&out[(size_t)(r0 + ty * 8 + i) * N_NODES + c0 + tx * 4] = v;
    }
}

// ---------------- launch --------------------------------------------------
extern "C" void kernel_launch(void* const* d_in, const int* in_sizes, int n_in,
                              void* d_out, int out_size) {
    const float* x        = (const float*)d_in[0];
    const float* m        = (const float*)d_in[2];
    const float* W1       = (const float*)d_in[3];
    const float* a_self1  = (const float*)d_in[4];
    const float* a_neigh1 = (const float*)d_in[5];
    const float* W2       = (const float*)d_in[6];
    const float* a_self2  = (const float*)d_in[7];
    const float* a_neigh2 = (const float*)d_in[8];
    float* out = (float*)d_out;

    float *h1, *h2, *z, *s1p, *t1p, *s2, *t2, *ew;
    int *cnt, *ej;
    cudaGetSymbolAddress((void**)&h1,  g_h1);
    cudaGetSymbolAddress((void**)&h2,  g_h2);
    cudaGetSymbolAddress((void**)&z,   g_z);
    cudaGetSymbolAddress((void**)&s1p, g_s1p);
    cudaGetSymbolAddress((void**)&t1p, g_t1p);
    cudaGetSymbolAddress((void**)&s2,  g_s2);
    cudaGetSymbolAddress((void**)&t2,  g_t2);
    cudaGetSymbolAddress((void**)&cnt, g_cnt);
    cudaGetSymbolAddress((void**)&ej,  g_ej);
    cudaGetSymbolAddress((void**)&ew,  g_ew);

    cudaFuncSetAttribute(gemm_edges, cudaFuncAttributeMaxDynamicSharedMemorySize, DYN_SMEM);
    gemm_edges<<<GEMM_BLOCKS + N_NODES, 256, DYN_SMEM>>>(x, W1, a_self1, a_neigh1,
                                                         h1, s1p, t1p, m, cnt, ej, ew);
    att1_fused<<<N_NODES / 8, 256>>>(cnt, ej, ew, h1, s1p, t1p, W2, a_self2, a_neigh2, h2, s2, t2);
    att2_fused<<<N_NODES / 8, 256>>>(cnt, ej, ew, h2, s2, t2, z, out + (size_t)N_NODES * N_NODES);
    {
        dim3 grid(N_NODES / 128, N_NODES / 64);
        decoder<<<grid, 256>>>(z, out);
    }
}

// round 11
// speedup vs baseline: 1.0600x; 1.0600x over previous
#include <cuda_runtime.h>
#include <math.h>
#include <stdint.h>

#define N_NODES 4096
#define F_IN    1024
#define HID     256
#define OUT_D   16
#define ALPHA   0.2f
#define NEG_INF (-3.4e38f)
#define MAXE    64
#define SPLITK  2
#define GEMM_BLOCKS ((HID / 128) * (N_NODES / 64) * SPLITK)   // 256
#define A_STR   36
#define B_STR   136
#define ABUF_FLOATS (2 * 64 * A_STR)
#define BBUF_FLOATS (2 * 32 * B_STR)
#define DYN_SMEM ((ABUF_FLOATS + BBUF_FLOATS) * 4)  // 53248

// ---------------- scratch (device globals; no allocation) ----------------
__device__ float g_P [SPLITK * N_NODES * HID];
__device__ float g_h1[N_NODES * HID];
__device__ float g_h2[N_NODES * OUT_D];
__device__ float g_z [N_NODES * OUT_D];
__device__ float g_s1[N_NODES], g_t1[N_NODES];
__device__ float g_s2[N_NODES], g_t2[N_NODES];
__device__ int   g_cnt[N_NODES];
__device__ int   g_ej [N_NODES * MAXE];
__device__ float g_ew [N_NODES * MAXE];

// ================= tf32 / cp.async helpers ================================
__device__ __forceinline__ uint32_t cvt_tf32(float x) {
    uint32_t r;
    asm("cvt.rna.tf32.f32 %0, %1;" : "=r"(r) : "f"(x));
    return r;
}
__device__ __forceinline__ void mma_tf32(float c[4], uint32_t a0, uint32_t a1,
                                         uint32_t a2, uint32_t a3,
                                         uint32_t b0, uint32_t b1) {
    asm volatile(
        "mma.sync.aligned.m16n8k8.row.col.f32.tf32.tf32.f32 "
        "{%0,%1,%2,%3}, {%4,%5,%6,%7}, {%8,%9}, {%0,%1,%2,%3};"
        : "+f"(c[0]), "+f"(c[1]), "+f"(c[2]), "+f"(c[3])
        : "r"(a0), "r"(a1), "r"(a2), "r"(a3), "r"(b0), "r"(b1));
}
__device__ __forceinline__ void cp16(uint32_t smem_dst, const float* gmem_src) {
    asm volatile("cp.async.cg.shared.global [%0], [%1], 16;" :: "r"(smem_dst), "l"(gmem_src));
}
__device__ __forceinline__ void cp_commit() {
    asm volatile("cp.async.commit_group;");
}
template <int N>
__device__ __forceinline__ void cp_wait() {
    asm volatile("cp.async.wait_group %0;" :: "n"(N));
}

// ================= f32x2 packed helpers (sm_100+) =========================
__device__ __forceinline__ unsigned long long splat2(float x) {
    unsigned long long r;
    asm("mov.b64 %0, {%1, %1};" : "=l"(r) : "f"(x));
    return r;
}
__device__ __forceinline__ unsigned long long fma2(unsigned long long a,
                                                   unsigned long long b,
                                                   unsigned long long c) {
    unsigned long long d;
    asm("fma.rn.f32x2 %0, %1, %2, %3;" : "=l"(d) : "l"(a), "l"(b), "l"(c));
    return d;
}
__device__ __forceinline__ unsigned long long mul2(unsigned long long a,
                                                   unsigned long long b) {
    unsigned long long d;
    asm("mul.rn.f32x2 %0, %1, %2;" : "=l"(d) : "l"(a), "l"(b));
    return d;
}
__device__ __forceinline__ void unpack2(unsigned long long v, float& lo, float& hi) {
    asm("mov.b64 {%0, %1}, %2;" : "=f"(lo), "=f"(hi) : "l"(v));
}

// ====== FUSED: blocks [0,256) tf32 GEMM split-K=2 (cp.async pipelined);
//        blocks [256,4352) edge scan ======================================
__global__ void __launch_bounds__(256) gemm_edges(
        const float* __restrict__ A, const float* __restrict__ B,
        float* __restrict__ P,
        const float* __restrict__ M, int* __restrict__ cnt,
        int* __restrict__ ej, float* __restrict__ ew) {
    extern __shared__ float dsm[];
    __shared__ int wsum[8], wbase[8];

    int bid = blockIdx.x, tid = threadIdx.x;
    if (bid < GEMM_BLOCKS) {
        float* Asf = dsm;
        float* Bsf = dsm + ABUF_FLOATS;
        uint32_t sa_base = (uint32_t)__cvta_generic_to_shared(Asf);
        uint32_t sb_base = (uint32_t)__cvta_generic_to_shared(Bsf);

        int bx = bid & 1;
        int by = (bid >> 1) & 63;
        int bz = bid >> 7;
        int warp = tid >> 5, lane = tid & 31;
        int grp = lane >> 2, tid4 = lane & 3;
        int wm = warp >> 2, wn = warp & 3;
        int rowBase = by * 64, colBase = bx * 128;
        int kBeg = bz * (F_IN / SPLITK);
        const int NIT = (F_IN / SPLITK) / 32;

        int a_r0 = tid >> 3,          a_c0 = (tid & 7) * 4;
        int a_r1 = (tid + 256) >> 3;
        int b_r0 = tid >> 5,          b_c0 = (tid & 31) * 4;
        int b_r1 = b_r0 + 8, b_r2 = b_r0 + 16, b_r3 = b_r0 + 24;

        float acc[2][4][4];
#pragma unroll
        for (int mt = 0; mt < 2; mt++)
#pragma unroll
            for (int nt = 0; nt < 4; nt++)
#pragma unroll
                for (int q = 0; q < 4; q++) acc[mt][nt][q] = 0.f;

        {
            int k0 = kBeg;
            cp16(sa_base + (uint32_t)((a_r0 * A_STR + a_c0) * 4),
                 &A[(size_t)(rowBase + a_r0) * F_IN + k0 + a_c0]);
            cp16(sa_base + (uint32_t)((a_r1 * A_STR + a_c0) * 4),
                 &A[(size_t)(rowBase + a_r1) * F_IN + k0 + a_c0]);
            cp16(sb_base + (uint32_t)((b_r0 * B_STR + b_c0) * 4),
                 &B[(size_t)(k0 + b_r0) * HID + colBase + b_c0]);
            cp16(sb_base + (uint32_t)((b_r1 * B_STR + b_c0) * 4),
                 &B[(size_t)(k0 + b_r1) * HID + colBase + b_c0]);
            cp16(sb_base + (uint32_t)((b_r2 * B_STR + b_c0) * 4),
                 &B[(size_t)(k0 + b_r2) * HID + colBase + b_c0]);
            cp16(sb_base + (uint32_t)((b_r3 * B_STR + b_c0) * 4),
                 &B[(size_t)(k0 + b_r3) * HID + colBase + b_c0]);
            cp_commit();
        }

        for (int it = 0; it < NIT; it++) {
            int cur = it & 1, nxt = cur ^ 1;
            if (it + 1 < NIT) {
                int k0 = kBeg + (it + 1) * 32;
                uint32_t ao = (uint32_t)(nxt * 64 * A_STR * 4);
                uint32_t bo = (uint32_t)(nxt * 32 * B_STR * 4);
                cp16(sa_base + ao + (uint32_t)((a_r0 * A_STR + a_c0) * 4),
                     &A[(size_t)(rowBase + a_r0) * F_IN + k0 + a_c0]);
                cp16(sa_base + ao + (uint32_t)((a_r1 * A_STR + a_c0) * 4),
                     &A[(size_t)(rowBase + a_r1) * F_IN + k0 + a_c0]);
                cp16(sb_base + bo + (uint32_t)((b_r0 * B_STR + b_c0) * 4),
                     &B[(size_t)(k0 + b_r0) * HID + colBase + b_c0]);
                cp16(sb_base + bo + (uint32_t)((b_r1 * B_STR + b_c0) * 4),
                     &B[(size_t)(k0 + b_r1) * HID + colBase + b_c0]);
                cp16(sb_base + bo + (uint32_t)((b_r2 * B_STR + b_c0) * 4),
                     &B[(size_t)(k0 + b_r2) * HID + colBase + b_c0]);
                cp16(sb_base + bo + (uint32_t)((b_r3 * B_STR + b_c0) * 4),
                     &B[(size_t)(k0 + b_r3) * HID + colBase + b_c0]);
                cp_commit();
                cp_wait<1>();
            } else {
                cp_wait<0>();
            }
            __syncthreads();

            const float* Ab = Asf + cur * 64 * A_STR;
            const float* Bb = Bsf + cur * 32 * B_STR;
#pragma unroll
            for (int kk = 0; kk < 32; kk += 8) {
                uint32_t a[2][4], b[4][2];
#pragma unroll
                for (int mt = 0; mt < 2; mt++) {
                    int r0 = wm * 32 + mt * 16 + grp;
                    a[mt][0] = cvt_tf32(Ab[r0 * A_STR + kk + tid4]);
                    a[mt][1] = cvt_tf32(Ab[(r0 + 8) * A_STR + kk + tid4]);
                    a[mt][2] = cvt_tf32(Ab[r0 * A_STR + kk + tid4 + 4]);
                    a[mt][3] = cvt_tf32(Ab[(r0 + 8) * A_STR + kk + tid4 + 4]);
                }
#pragma unroll
                for (int nt = 0; nt < 4; nt++) {
                    int cb = wn * 32 + nt * 8 + grp;
                    b[nt][0] = cvt_tf32(Bb[(kk + tid4) * B_STR + cb]);
                    b[nt][1] = cvt_tf32(Bb[(kk + tid4 + 4) * B_STR + cb]);
                }
#pragma unroll
                for (int mt = 0; mt < 2; mt++)
#pragma unroll
                    for (int nt = 0; nt < 4; nt++)
                        mma_tf32(acc[mt][nt], a[mt][0], a[mt][1], a[mt][2], a[mt][3],
                                 b[nt][0], b[nt][1]);
            }
            __syncthreads();
        }

        float* dst = P + (size_t)bz * N_NODES * HID;
#pragma unroll
        for (int mt = 0; mt < 2; mt++) {
            int r0 = rowBase + wm * 32 + mt * 16 + grp;
#pragma unroll
            for (int nt = 0; nt < 4; nt++) {
                int c0 = colBase + wn * 32 + nt * 8 + tid4 * 2;
                *(float2*)&dst[(size_t)r0 * HID + c0]       = make_float2(acc[mt][nt][0], acc[mt][nt][1]);
                *(float2*)&dst[(size_t)(r0 + 8) * HID + c0] = make_float2(acc[mt][nt][2], acc[mt][nt][3]);
            }
        }
    } else {
        int i = bid - GEMM_BLOCKS;
        const float4* row = (const float4*)(M + (size_t)i * N_NODES);
        float4 v[4];
        int local = 0;
#pragma unroll
        for (int q = 0; q < 4; q++) {
            v[q] = __ldcs(&row[tid * 4 + q]);
            local += (v[q].x > 0.f) + (v[q].y > 0.f) + (v[q].z > 0.f) + (v[q].w > 0.f);
        }
        int lane = tid & 31, warp = tid >> 5;
        int sc = local;
#pragma unroll
        for (int o = 1; o < 32; o <<= 1) {
            int nb = __shfl_up_sync(0xffffffffu, sc, o);
            if (lane >= o) sc += nb;
        }
        if (lane == 31) wsum[warp] = sc;
        __syncthreads();
        if (tid < 8) {
            int b = 0;
            for (int w = 0; w < tid; w++) b += wsum[w];
            wbase[tid] = b;
        }
        __syncthreads();
        int off = wbase[warp] + sc - local;
        int rb = i * MAXE;
        int j0 = tid * 16;
#pragma unroll
        for (int q = 0; q < 4; q++) {
            float vals[4] = {v[q].x, v[q].y, v[q].z, v[q].w};
#pragma unroll
            for (int r = 0; r < 4; r++) {
                if (vals[r] > 0.f) {
                    if (off < MAXE) { ej[rb + off] = j0 + q * 4 + r; ew[rb + off] = vals[r]; }
                    off++;
                }
            }
        }
        if (tid == 0) {
            int total = wbase[7] + wsum[7];
            cnt[i] = total < MAXE ? total : MAXE;
        }
    }
}

// ============= combine split-K partials + row dots (h1, s1, t1) ===========
__global__ void rowdot(const float* __restrict__ P,
                       const float* __restrict__ as_, const float* __restrict__ an_,
                       float* __restrict__ H, float* __restrict__ s, float* __restrict__ t) {
    int rowi = blockIdx.x * 8 + (threadIdx.x >> 5);
    int lane = threadIdx.x & 31;
    const float4* p0 = (const float4*)(P + (size_t)rowi * HID);
    const size_t stride4 = (size_t)N_NODES * HID / 4;
    float4* h = (float4*)(H + (size_t)rowi * HID);
    float ss = 0.f, tt = 0.f;
#pragma unroll
    for (int q = 0; q < 2; q++) {
        int k4 = lane + q * 32;
        float4 a = p0[k4];
        float4 b = p0[k4 + stride4];
        float4 vv = make_float4(a.x + b.x, a.y + b.y, a.z + b.z, a.w + b.w);
        h[k4] = vv;
        float4 va = *(const float4*)&as_[k4 * 4];
        float4 vn = *(const float4*)&an_[k4 * 4];
        ss += vv.x * va.x + vv.y * va.y + vv.z * va.z + vv.w * va.w;
        tt += vv.x * vn.x + vv.y * vn.y + vv.z * vn.z + vv.w * vn.w;
    }
#pragma unroll
    for (int o = 16; o; o >>= 1) {
        ss += __shfl_down_sync(0xffffffffu, ss, o);
        tt += __shfl_down_sync(0xffffffffu, tt, o);
    }
    if (lane == 0) { s[rowi] = ss; t[rowi] = tt; }
}

// ====== layer-1 attention, warp-per-row ====================================
__device__ __forceinline__ float eluf(float x) { return x > 0.f ? x : expm1f(x); }

__global__ void __launch_bounds__(256) att1_fused(
        const int* __restrict__ cnt, const int* __restrict__ ej,
        const float* __restrict__ ew, const float* __restrict__ H,
        const float* __restrict__ s1, const float* __restrict__ t1,
        const float* __restrict__ W2,
        const float* __restrict__ as2, const float* __restrict__ an2,
        float* __restrict__ h2, float* __restrict__ s2, float* __restrict__ t2) {
    __shared__ float ws[8][MAXE];
    __shared__ int   jss[8][MAXE];
    int wl = threadIdx.x >> 5;
    int lane = threadIdx.x & 31;
    int i = blockIdx.x * 8 + wl;
    int n = cnt[i];
    float si = s1[i];

    float e0 = NEG_INF, e1 = NEG_INF;
    int j0 = 0, j1 = 0;
    if (lane < n) {
        j0 = ej[i * MAXE + lane];
        float w = ew[i * MAXE + lane];
        float e = (si + t1[j0]) * w;
        e0 = e >= 0.f ? e : ALPHA * e;
    }
    if (lane + 32 < n) {
        j1 = ej[i * MAXE + lane + 32];
        float w = ew[i * MAXE + lane + 32];
        float e = (si + t1[j1]) * w;
        e1 = e >= 0.f ? e : ALPHA * e;
    }
    float mx = fmaxf(e0, e1);
#pragma unroll
    for (int o = 16; o; o >>= 1) mx = fmaxf(mx, __shfl_xor_sync(0xffffffffu, mx, o));
    float w0 = (lane < n) ? __expf(e0 - mx) : 0.f;
    float w1 = (lane + 32 < n) ? __expf(e1 - mx) : 0.f;
    float sm = w0 + w1;
#pragma unroll
    for (int o = 16; o; o >>= 1) sm += __shfl_xor_sync(0xffffffffu, sm, o);
    float inv = 1.f / sm;
    ws[wl][lane] = w0 * inv;
    ws[wl][lane + 32] = w1 * inv;
    jss[wl][lane] = j0;
    jss[wl][lane + 32] = j1;
    __syncwarp();

    const float4* H4 = (const float4*)H;
    float4 acc0 = make_float4(0.f, 0.f, 0.f, 0.f);
    float4 acc1 = make_float4(0.f, 0.f, 0.f, 0.f);
    int n4 = (n + 3) & ~3;
    for (int p = 0; p < n4; p += 4) {
        float wA = ws[wl][p],     wB = ws[wl][p + 1];
        float wC = ws[wl][p + 2], wD = ws[wl][p + 3];
        size_t bA = (size_t)jss[wl][p] * 64,     bB = (size_t)jss[wl][p + 1] * 64;
        size_t bC = (size_t)jss[wl][p + 2] * 64, bD = (size_t)jss[wl][p + 3] * 64;
        float4 a0 = H4[bA + lane], a1 = H4[bA + 32 + lane];
        float4 b0 = H4[bB + lane], b1 = H4[bB + 32 + lane];
        float4 c0 = H4[bC + lane], c1 = H4[bC + 32 + lane];
        float4 d0 = H4[bD + lane], d1 = H4[bD + 32 + lane];
        acc0.x += wA * a0.x + wB * b0.x + wC * c0.x + wD * d0.x;
        acc0.y += wA * a0.y + wB * b0.y + wC * c0.y + wD * d0.y;
        acc0.z += wA * a0.z + wB * b0.z + wC * c0.z + wD * d0.z;
        acc0.w += wA * a0.w + wB * b0.w + wC * c0.w + wD * d0.w;
        acc1.x += wA * a1.x + wB * b1.x + wC * c1.x + wD * d1.x;
        acc1.y += wA * a1.y + wB * b1.y + wC * c1.y + wD * d1.y;
        acc1.z += wA * a1.z + wB * b1.z + wC * c1.z + wD * d1.z;
        acc1.w += wA * a1.w + wB * b1.w + wC * c1.w + wD * d1.w;
    }
    float o1v[8];
    o1v[0] = eluf(acc0.x); o1v[1] = eluf(acc0.y);
    o1v[2] = eluf(acc0.z); o1v[3] = eluf(acc0.w);
    o1v[4] = eluf(acc1.x); o1v[5] = eluf(acc1.y);
    o1v[6] = eluf(acc1.z); o1v[7] = eluf(acc1.w);

    float pa[16];
#pragma unroll
    for (int k = 0; k < 16; k++) pa[k] = 0.f;
#pragma unroll
    for (int half = 0; half < 2; half++) {
#pragma unroll
        for (int q = 0; q < 4; q++) {
            int c = half * 128 + 4 * lane + q;
            float ov = o1v[half * 4 + q];
            const float4* wr = (const float4*)&W2[c * OUT_D];
            float4 r0 = __ldg(wr), r1 = __ldg(wr + 1), r2 = __ldg(wr + 2), r3 = __ldg(wr + 3);
            pa[0] += ov * r0.x;  pa[1] += ov * r0.y;  pa[2] += ov * r0.z;  pa[3] += ov * r0.w;
            pa[4] += ov * r1.x;  pa[5] += ov * r1.y;  pa[6] += ov * r1.z;  pa[7] += ov * r1.w;
            pa[8] += ov * r2.x;  pa[9] += ov * r2.y;  pa[10] += ov * r2.z; pa[11] += ov * r2.w;
            pa[12] += ov * r3.x; pa[13] += ov * r3.y; pa[14] += ov * r3.z; pa[15] += ov * r3.w;
        }
    }
#pragma unroll
    for (int o = 16; o; o >>= 1)
#pragma unroll
        for (int k = 0; k < 16; k++)
            pa[k] += __shfl_xor_sync(0xffffffffu, pa[k], o);

    if (lane == 0) {
        *(float4*)&h2[(size_t)i * OUT_D]      = make_float4(pa[0], pa[1], pa[2], pa[3]);
        *(float4*)&h2[(size_t)i * OUT_D + 4]  = make_float4(pa[4], pa[5], pa[6], pa[7]);
        *(float4*)&h2[(size_t)i * OUT_D + 8]  = make_float4(pa[8], pa[9], pa[10], pa[11]);
        *(float4*)&h2[(size_t)i * OUT_D + 12] = make_float4(pa[12], pa[13], pa[14], pa[15]);
        float ps = 0.f, pt = 0.f;
#pragma unroll
        for (int k = 0; k < 16; k++) {
            ps += pa[k] * __ldg(&as2[k]);
            pt += pa[k] * __ldg(&an2[k]);
        }
        s2[i] = ps; t2[i] = pt;
    }
}

// ====== layer-2 attention + aggregate + ELU + L2-normalize (warp/row) ======
__global__ void att2_fused(const int* __restrict__ cnt, const int* __restrict__ ej,
                           const float* __restrict__ ew, const float* __restrict__ h2,
                           const float* __restrict__ s2, const float* __restrict__ t2,
                           float* __restrict__ z, float* __restrict__ zout) {
    __shared__ float ws[8][MAXE];
    __shared__ int   jss[8][MAXE];
    int wl = threadIdx.x >> 5;
    int lane = threadIdx.x & 31;
    int i = blockIdx.x * 8 + wl;
    int n = cnt[i];
    float si = s2[i];

    float e0 = NEG_INF, e1 = NEG_INF;
    int j0 = 0, j1 = 0;
    if (lane < n) {
        j0 = ej[i * MAXE + lane];
        float w = ew[i * MAXE + lane];
        float e = (si + t2[j0]) * w;
        e0 = e >= 0.f ? e : ALPHA * e;
    }
    if (lane + 32 < n) {
        j1 = ej[i * MAXE + lane + 32];
        float w = ew[i * MAXE + lane + 32];
        float e = (si + t2[j1]) * w;
        e1 = e >= 0.f ? e : ALPHA * e;
    }
    float mx = fmaxf(e0, e1);
#pragma unroll
    for (int o = 16; o; o >>= 1) mx = fmaxf(mx, __shfl_xor_sync(0xffffffffu, mx, o));
    float w0 = (lane < n) ? __expf(e0 - mx) : 0.f;
    float w1 = (lane + 32 < n) ? __expf(e1 - mx) : 0.f;
    float sm = w0 + w1;
#pragma unroll
    for (int o = 16; o; o >>= 1) sm += __shfl_xor_sync(0xffffffffu, sm, o);
    float inv = 1.f / sm;
    ws[wl][lane] = w0 * inv; ws[wl][lane + 32] = w1 * inv;
    jss[wl][lane] = j0; jss[wl][lane + 32] = j1;
    __syncwarp();

    int c = lane & 15, g = lane >> 4;
    float acc = 0.f;
    int n2 = (n + 1) & ~1;
    for (int p = g; p < n2; p += 2)
        acc += ws[wl][p] * h2[(size_t)jss[wl][p] * OUT_D + c];
    acc += __shfl_xor_sync(0xffffffffu, acc, 16);
    float o = eluf(acc);
    float sq = o * o;
#pragma unroll
    for (int off = 8; off; off >>= 1) sq += __shfl_xor_sync(0xffffffffu, sq, off);
    float invn = 1.f / fmaxf(sqrtf(sq), 1e-12f);
    float zz = o * invn;
    if (lane < 16) {
        z[(size_t)i * OUT_D + lane] = zz;
        zout[(size_t)i * OUT_D + lane] = zz;
    }
}

// ================= decoder: adj_pred = sigmoid(z @ z^T) ===================
// f32x2 FMA mainloop; zr re-read via 2 broadcast float4 LDS per k (register
// splats) instead of 8 scalar LDS — kills the L1 bottleneck. Streaming stores.
__global__ void __launch_bounds__(256, 4) decoder(const float* __restrict__ z,
                                                  float* __restrict__ out) {
    __shared__ float zr[16][64];
    __shared__ float zc[16][128];
    int tid = threadIdx.x;
    int r0 = blockIdx.y * 64, c0 = blockIdx.x * 128;
    for (int p = tid; p < 64 * 16; p += 256) {
        int r = p >> 4, k = p & 15;
        zr[k][r] = z[(size_t)(r0 + r) * OUT_D + k];
    }
    for (int p = tid; p < 128 * 16; p += 256) {
        int r = p >> 4, k = p & 15;
        zc[k][r] = z[(size_t)(c0 + r) * OUT_D + k];
    }
    __syncthreads();
    int tx = tid & 31;
    int ty = tid >> 5;

    unsigned long long acc2[8][2];
#pragma unroll
    for (int i = 0; i < 8; i++) { acc2[i][0] = 0ull; acc2[i][1] = 0ull; }

#pragma unroll
    for (int k = 0; k < 16; k++) {
        float4 arv0 = *(const float4*)&zr[k][ty * 8];       // broadcast LDS.128
        float4 arv1 = *(const float4*)&zr[k][ty * 8 + 4];   // broadcast LDS.128
        ulonglong2 bc2 = *(const ulonglong2*)&zc[k][tx * 4];
        unsigned long long ar2[8];
        ar2[0] = splat2(arv0.x); ar2[1] = splat2(arv0.y);
        ar2[2] = splat2(arv0.z); ar2[3] = splat2(arv0.w);
        ar2[4] = splat2(arv1.x); ar2[5] = splat2(arv1.y);
        ar2[6] = splat2(arv1.z); ar2[7] = splat2(arv1.w);
#pragma unroll
        for (int i = 0; i < 8; i++) {
            acc2[i][0] = fma2(ar2[i], bc2.x, acc2[i][0]);
            acc2[i][1] = fma2(ar2[i], bc2.y, acc2[i][1]);
        }
    }

    const unsigned long long C8 = splat2(2.1357251e-5f);
    const unsigned long long C6 = splat2(-2.1081349e-4f);
    const unsigned long long C4 = splat2(2.0833333e-3f);
    const unsigned long long C2 = splat2(-2.0833333e-2f);
    const unsigned long long C0 = splat2(0.25f);
    const unsigned long long HALF = splat2(0.5f);

#pragma unroll
    for (int i = 0; i < 8; i++) {
        float4 v;
#pragma unroll
        for (int j = 0; j < 2; j++) {
            unsigned long long x = acc2[i][j];
            unsigned long long u = mul2(x, x);
            unsigned long long p = fma2(u, C8, C6);
            p = fma2(u, p, C4);
            p = fma2(u, p, C2);
            p = fma2(u, p, C0);
            p = fma2(x, p, HALF);
            if (j == 0) unpack2(p, v.x, v.y);
            else        unpack2(p, v.z, v.w);
        }
        __stcs((float4*)&out[(size_t)(r0 + ty * 8 + i) * N_NODES + c0 + tx * 4], v);
    }
}

// ---------------- launch --------------------------------------------------
extern "C" void kernel_launch(void* const* d_in, const int* in_sizes, int n_in,
                              void* d_out, int out_size) {
    const float* x        = (const float*)d_in[0];
    const float* m        = (const float*)d_in[2];
    const float* W1       = (const float*)d_in[3];
    const float* a_self1  = (const float*)d_in[4];
    const float* a_neigh1 = (const float*)d_in[5];
    const float* W2       = (const float*)d_in[6];
    const float* a_self2  = (const float*)d_in[7];
    const float* a_neigh2 = (const float*)d_in[8];
    float* out = (float*)d_out;

    float *P, *h1, *h2, *z, *s1, *t1, *s2, *t2, *ew;
    int *cnt, *ej;
    cudaGetSymbolAddress((void**)&P,   g_P);
    cudaGetSymbolAddress((void**)&h1,  g_h1);
    cudaGetSymbolAddress((void**)&h2,  g_h2);
    cudaGetSymbolAddress((void**)&z,   g_z);
    cudaGetSymbolAddress((void**)&s1,  g_s1);
    cudaGetSymbolAddress((void**)&t1,  g_t1);
    cudaGetSymbolAddress((void**)&s2,  g_s2);
    cudaGetSymbolAddress((void**)&t2,  g_t2);
    cudaGetSymbolAddress((void**)&cnt, g_cnt);
    cudaGetSymbolAddress((void**)&ej,  g_ej);
    cudaGetSymbolAddress((void**)&ew,  g_ew);

    cudaFuncSetAttribute(gemm_edges, cudaFuncAttributeMaxDynamicSharedMemorySize, DYN_SMEM);
    gemm_edges<<<GEMM_BLOCKS + N_NODES, 256, DYN_SMEM>>>(x, W1, P, m, cnt, ej, ew);
    rowdot<<<N_NODES / 8, 256>>>(P, a_self1, a_neigh1, h1, s1, t1);
    att1_fused<<<N_NODES / 8, 256>>>(cnt, ej, ew, h1, s1, t1, W2, a_self2, a_neigh2, h2, s2, t2);
    att2_fused<<<N_NODES / 8, 256>>>(cnt, ej, ew, h2, s2, t2, z, out + (size_t)N_NODES * N_NODES);
    {
        dim3 grid(N_NODES / 128, N_NODES / 64);
        decoder<<<grid, 256>>>(z, out);
    }
}